// round 9
// baseline (speedup 1.0000x reference)
#include <cuda_runtime.h>
#include <cstdint>

#define N 256
#define NP 65536u
#define NVOX 16777216u
#define YC 64
#define NSTEPS 70            // 14 * 5; epilogue at t in [4,67]

// ---------------- packed f32x2 helpers (sm_103a) ----------------
union F2U { float2 f; unsigned long long u; };
__device__ __forceinline__ float2 f2add(float2 a, float2 b) {
    F2U x, y, r; x.f = a; y.f = b;
    asm("add.rn.f32x2 %0,%1,%2;" : "=l"(r.u) : "l"(x.u), "l"(y.u));
    return r.f;
}
__device__ __forceinline__ float2 f2mul(float2 a, float2 b) {
    F2U x, y, r; x.f = a; y.f = b;
    asm("mul.rn.f32x2 %0,%1,%2;" : "=l"(r.u) : "l"(x.u), "l"(y.u));
    return r.f;
}
__device__ __forceinline__ float2 f2fma(float2 a, float2 b, float2 c) {
    F2U x, y, zc, r; x.f = a; y.f = b; zc.f = c;
    asm("fma.rn.f32x2 %0,%1,%2,%3;" : "=l"(r.u) : "l"(x.u), "l"(y.u), "l"(zc.u));
    return r.f;
}
__device__ __forceinline__ float2 f2set(float a, float b) { float2 r; r.x = a; r.y = b; return r; }

// ===========================================================================
// Fused NCC forces, 2 voxels/thread, minimized shared traffic.
// CTA = 128 threads spanning full x-row at fixed z; marches y.
// Own-x gradient operands live in register delay rings; smem used only for
// x-neighbor exchange (quantities + center row). Phase-staggered accumulators
// give exact y-box sums with static indexing.
// ===========================================================================
__global__ __launch_bounds__(128, 3) void ncc_fused3_kernel(
    const float* __restrict__ img, const float* __restrict__ ref,
    float* __restrict__ out)
{
    __shared__ float qz[2][5][264];   // double-buffered z-summed quantity rows, pad 2
    __shared__ float cc[5][2][260];   // 5-slot center-row ring (img,ref), pad 2

    const int t0 = threadIdx.x;       // 0..127
    const int x0 = t0 << 1;
    const int z  = blockIdx.x;
    const int y0 = blockIdx.y * YC;

    // zero pads once: qz idx {0,1,258,259} x 2 bufs x 5 q = 40; cc same idx x 5 x 2 = 40
    if (t0 < 40) {
        int b = t0 / 20, rem = t0 % 20, q = rem / 4, p = rem & 3;
        int xi = (p < 2) ? p : (256 + p);
        qz[b][q][xi] = 0.f;
    } else if (t0 < 80) {
        int u = t0 - 40;
        int j = u / 8, rem = u % 8, ch = rem / 4, p = rem & 3;
        int xi = (p < 2) ? p : (256 + p);
        cc[j][ch][xi] = 0.f;
    }

    bool pz[5]; unsigned pb[5];
#pragma unroll
    for (int p = 0; p < 5; p++) {
        int zz = z - 2 + p;
        pz[p] = (zz >= 0) && (zz < N);
        pb[p] = (unsigned)(pz[p] ? zz : 0) * NP + (unsigned)x0;
    }

    const float2 zero2 = f2set(0.f, 0.f);
    const float2 km1   = f2set(-1.f, -1.f);
    const float2 km2   = f2set(-2.f, -2.f);
    const float2 k05   = f2set(0.5f, 0.5f);
    const float2 k2    = f2set(2.f, 2.f);
    const float2 k125  = f2set(125.f, 125.f);
    const float2 kinv  = f2set(1.f / 125.f, 1.f / 125.f);
    const float2 keps  = f2set(1e-6f, 1e-6f);

    // phase-staggered y-box accumulators: acc[q][t%5] completes at step t
    float2 acc[5][5];
#pragma unroll
    for (int q = 0; q < 5; q++)
#pragma unroll
        for (int k = 0; k < 5; k++) acc[q][k] = zero2;

    // register delay rings (own x pair)
    float2 cI[4], cR[4];              // center plane z: rows t-3..t after push
    float2 zpI[3], zpR[3], zmI[3], zmR[3];  // planes z+1 / z-1: rows t-2..t
#pragma unroll
    for (int k = 0; k < 4; k++) { cI[k] = zero2; cR[k] = zero2; }
#pragma unroll
    for (int k = 0; k < 3; k++) { zpI[k] = zero2; zpR[k] = zero2; zmI[k] = zero2; zmR[k] = zero2; }

    // prefetch row t=0 (yl = y0-2)
    float2 pvi[5], pvr[5];
    {
        int yl = y0 - 2;
        bool inr = (yl >= 0);
        unsigned ro = (unsigned)(inr ? yl : 0) * N;
#pragma unroll
        for (int p = 0; p < 5; p++) {
            bool ok = inr && pz[p];
            pvi[p] = ok ? __ldg((const float2*)(img + pb[p] + ro)) : zero2;
            pvr[p] = ok ? __ldg((const float2*)(ref + pb[p] + ro)) : zero2;
        }
    }
    __syncthreads();

    int buf = 0;
    for (int tb = 0; tb < 14; ++tb) {
#pragma unroll
        for (int j = 0; j < 5; ++j) {
            const int t = tb * 5 + j;

            // ---- z-summed quantities (packed) ----
            const float2 v0 = pvi[0], v1 = pvi[1], v2 = pvi[2], v3 = pvi[3], v4 = pvi[4];
            const float2 r0 = pvr[0], r1 = pvr[1], r2 = pvr[2], r3 = pvr[3], r4 = pvr[4];
            const float2 qi  = f2add(f2add(f2add(v0, v1), f2add(v2, v3)), v4);
            const float2 qr  = f2add(f2add(f2add(r0, r1), f2add(r2, r3)), r4);
            const float2 qii = f2fma(v4, v4, f2fma(v3, v3, f2fma(v2, v2, f2fma(v1, v1, f2mul(v0, v0)))));
            const float2 qrr = f2fma(r4, r4, f2fma(r3, r3, f2fma(r2, r2, f2fma(r1, r1, f2mul(r0, r0)))));
            const float2 qir = f2fma(v4, r4, f2fma(v3, r3, f2fma(v2, r2, f2fma(v1, r1, f2mul(v0, r0)))));

            *(float2*)&qz[buf][0][x0 + 2] = qi;
            *(float2*)&qz[buf][1][x0 + 2] = qr;
            *(float2*)&qz[buf][2][x0 + 2] = qii;
            *(float2*)&qz[buf][3][x0 + 2] = qrr;
            *(float2*)&qz[buf][4][x0 + 2] = qir;
            *(float2*)&cc[j][0][x0 + 2] = v2;   // center row for x-neighbor exchange
            *(float2*)&cc[j][1][x0 + 2] = r2;

            // ---- push register rings ----
#pragma unroll
            for (int k = 0; k < 3; k++) { cI[k] = cI[k+1]; cR[k] = cR[k+1]; }
            cI[3] = v2; cR[3] = r2;
#pragma unroll
            for (int k = 0; k < 2; k++) {
                zpI[k] = zpI[k+1]; zpR[k] = zpR[k+1];
                zmI[k] = zmI[k+1]; zmR[k] = zmR[k+1];
            }
            zpI[2] = v3; zpR[2] = r3;
            zmI[2] = v1; zmR[2] = r1;

            // ---- prefetch next row ----
            if (t + 1 < NSTEPS) {
                int yn = y0 - 1 + t;
                bool inr = (yn >= 0) && (yn < N);
                unsigned ro = (unsigned)(inr ? yn : 0) * N;
#pragma unroll
                for (int p = 0; p < 5; p++) {
                    bool ok = inr && pz[p];
                    pvi[p] = ok ? __ldg((const float2*)(img + pb[p] + ro)) : zero2;
                    pvr[p] = ok ? __ldg((const float2*)(ref + pb[p] + ro)) : zero2;
                }
            }
            __syncthreads();

            // ---- x-box (own value from regs, neighbors from smem) ----
            const float2 qown[5] = { qi, qr, qii, qrr, qir };
#pragma unroll
            for (int q = 0; q < 5; q++) {
                float2 a = *(const float2*)&qz[buf][q][x0];       // x0-2, x0-1
                float2 c = *(const float2*)&qz[buf][q][x0 + 4];   // x0+2, x0+3
                float2 b = qown[q];
                float s = a.y + b.x + b.y + c.x;
                float2 bx = f2set(s + a.x, s + c.y);
                // add to all 5 staggered accumulators
#pragma unroll
                for (int k = 0; k < 5; k++) acc[q][k] = f2add(acc[q][k], bx);
            }
            buf ^= 1;

            // ---- epilogue for y = y0 + t - 4 (acc[.][j] just completed) ----
            if (t >= 4 && t < 68) {
                const int y = y0 + t - 4;
                const int jc = (j + 3) % 5;   // cc slot of row y

                const float2 sum_i = acc[0][j], sum_r = acc[1][j];
                const float2 sum_ii = acc[2][j], sum_rr = acc[3][j], sum_ir = acc[4][j];

                const float2 mi = f2mul(sum_i, kinv);   // faithful: ref mean uses sum_i
                const float2 t1 = f2mul(mi, k125);
                const float2 varr = f2fma(mi, f2fma(sum_r, km2, t1), sum_rr);
                const float2 vari = f2fma(mi, f2fma(sum_i, km2, t1), sum_ii);
                const float2 cross = f2fma(mi, f2fma(f2add(sum_i, sum_r), km1, t1), sum_ir);

                // centers (own pair) from rings: row y = cI[1]; y+1 = cI[2]; y-1 = cI[0]
                const float2 ciI = cI[1], ciR = cR[1];
                const float2 ypI = cI[2], ypR = cR[2];
                const float2 ymI = cI[0], ymR = cR[0];
                const float2 zpi = zpI[0], zpr = zpR[0];
                const float2 zmi = zmI[0], zmr = zmR[0];

                // x neighbors from cc
                const float2 prevI = *(const float2*)&cc[jc][0][x0];       // x0-2, x0-1
                const float2 nextI = *(const float2*)&cc[jc][0][x0 + 4];   // x0+2, x0+3
                const float2 prevR = *(const float2*)&cc[jc][1][x0];
                const float2 nextR = *(const float2*)&cc[jc][1][x0 + 4];

                const float2 xlI = f2set(prevI.y, ciI.x);   // x-1 values for pair
                const float2 xrI = f2set(ciI.y, nextI.x);   // x+1 values
                const float2 xlR = f2set(prevR.y, ciR.x);
                const float2 xrR = f2set(ciR.y, nextR.x);

                float2 gxi = f2mul(f2fma(xlI, km1, xrI), k05);
                float2 gxr = f2mul(f2fma(xlR, km1, xrR), k05);
                float2 gyi = f2mul(f2fma(ymI, km1, ypI), k05);
                float2 gyr = f2mul(f2fma(ymR, km1, ypR), k05);
                float2 gzi = f2mul(f2fma(zmi, km1, zpi), k05);
                float2 gzr = f2mul(f2fma(zmr, km1, zpr), k05);

                if (t0 == 0)   { gxi.x = ciI.y - ciI.x; gxr.x = ciR.y - ciR.x; }
                if (t0 == 127) { gxi.y = ciI.y - ciI.x; gxr.y = ciR.y - ciR.x; }
                if (y == 0)     { gyi = f2fma(ciI, km1, ypI); gyr = f2fma(ciR, km1, ypR); }
                if (y == N - 1) { gyi = f2fma(ymI, km1, ciI); gyr = f2fma(ymR, km1, ciR); }
                if (z == 0)     { gzi = f2fma(ciI, km1, zpi); gzr = f2fma(ciR, km1, zpr); }
                if (z == N - 1) { gzi = f2fma(zmi, km1, ciI); gzr = f2fma(zmr, km1, ciR); }

                const float2 gd = f2mul(f2add(gzi, gzr), k05);
                const float2 gh = f2mul(f2add(gyi, gyr), k05);
                const float2 gw = f2mul(f2add(gxi, gxr), k05);

                const float2 den = f2fma(vari, varr, keps);
                float2 rden, cv;
                rden.x = __fdividef(1.f, den.x);
                rden.y = __fdividef(1.f, den.y);
                cv.x = __fdividef(cross.x, varr.x);
                cv.y = __fdividef(cross.y, varr.y);
                const float2 inner = f2fma(f2mul(cv, km1), ciR, ciI);
                const float2 fac = f2mul(f2mul(k2, cross), f2mul(rden, inner));
                const float2 nfac = f2mul(fac, km1);

                const unsigned idx = (unsigned)z * NP + (unsigned)y * N + (unsigned)x0;
                *(float2*)(out + idx)             = f2mul(nfac, gd);
                *(float2*)(out + NVOX + idx)      = f2mul(nfac, gh);
                *(float2*)(out + 2u * NVOX + idx) = f2mul(nfac, gw);
            }
            // reset the completed accumulator (always, to keep phases aligned)
#pragma unroll
            for (int q = 0; q < 5; q++) acc[q][j] = zero2;
        }
    }
}

// ---------------------------------------------------------------------------
extern "C" void kernel_launch(void* const* d_in, const int* in_sizes, int n_in,
                              void* d_out, int out_size)
{
    const float* img = (const float*)d_in[0];   // image
    const float* ref = (const float*)d_in[2];   // reference_image
    float* out = (float*)d_out;

    dim3 block(128, 1, 1);
    dim3 grid(N, N / YC, 1);    // 256 z x 4 y-chunks
    ncc_fused3_kernel<<<grid, block>>>(img, ref, out);
}

// round 10
// speedup vs baseline: 1.1723x; 1.1723x over previous
#include <cuda_runtime.h>
#include <cstdint>

#define N 256
#define NP 65536u
#define NVOX 16777216u
#define YC 64
#define NSTEPS 70            // 14 * 5; epilogue at t in [4,67]

// ---------------- packed f32x2 helpers (sm_103a) ----------------
union F2U { float2 f; unsigned long long u; };
__device__ __forceinline__ float2 f2add(float2 a, float2 b) {
    F2U x, y, r; x.f = a; y.f = b;
    asm("add.rn.f32x2 %0,%1,%2;" : "=l"(r.u) : "l"(x.u), "l"(y.u));
    return r.f;
}
__device__ __forceinline__ float2 f2mul(float2 a, float2 b) {
    F2U x, y, r; x.f = a; y.f = b;
    asm("mul.rn.f32x2 %0,%1,%2;" : "=l"(r.u) : "l"(x.u), "l"(y.u));
    return r.f;
}
__device__ __forceinline__ float2 f2fma(float2 a, float2 b, float2 c) {
    F2U x, y, zc, r; x.f = a; y.f = b; zc.f = c;
    asm("fma.rn.f32x2 %0,%1,%2,%3;" : "=l"(r.u) : "l"(x.u), "l"(y.u), "l"(zc.u));
    return r.f;
}
__device__ __forceinline__ float2 f2set(float a, float b) { float2 r; r.x = a; r.y = b; return r; }

// ===========================================================================
// Fused NCC forces, 2 voxels/thread. All delay state either in statically
// indexed register ring (y-box values) or in the depth-5 smem row ring cc
// (center + z+-1 rows). No register ring shifts, no staggered accumulators.
// ===========================================================================
__global__ __launch_bounds__(128, 4) void ncc_fused4_kernel(
    const float* __restrict__ img, const float* __restrict__ ref,
    float* __restrict__ out)
{
    __shared__ float qz[2][5][264];   // double-buffered z-summed quantity rows, pad 2
    __shared__ float cc[5][6][260];   // row ring: {v2,r2,v3,r3,v1,r1}, pad 2

    const int t0 = threadIdx.x;       // 0..127
    const int x0 = t0 << 1;
    const int z  = blockIdx.x;
    const int y0 = blockIdx.y * YC;

    // zero pads once
    if (t0 < 40) {   // qz: 2 bufs x 5 q x 4 pads
        int b = t0 / 20, rem = t0 % 20, q = rem / 4, p = rem & 3;
        int xi = (p < 2) ? p : (256 + p);
        qz[b][q][xi] = 0.f;
    }
    if (t0 < 120) {  // cc: 5 slots x 6 ch x 4 pads
        int j = t0 / 24, rem = t0 % 24, ch = rem / 4, p = rem & 3;
        int xi = (p < 2) ? p : (256 + p);
        cc[j][ch][xi] = 0.f;
    }

    bool pz[5]; unsigned pb[5];
#pragma unroll
    for (int p = 0; p < 5; p++) {
        int zz = z - 2 + p;
        pz[p] = (zz >= 0) && (zz < N);
        pb[p] = (unsigned)(pz[p] ? zz : 0) * NP + (unsigned)x0;
    }

    const float2 zero2 = f2set(0.f, 0.f);
    const float2 km1   = f2set(-1.f, -1.f);
    const float2 km2   = f2set(-2.f, -2.f);
    const float2 k05   = f2set(0.5f, 0.5f);
    const float2 k2    = f2set(2.f, 2.f);
    const float2 k125  = f2set(125.f, 125.f);
    const float2 kinv  = f2set(1.f / 125.f, 1.f / 125.f);
    const float2 keps  = f2set(1e-6f, 1e-6f);

    // y-box value ring, statically indexed by unroll phase j (no shifts)
    float2 ring[5][5];
#pragma unroll
    for (int q = 0; q < 5; q++)
#pragma unroll
        for (int k = 0; k < 5; k++) ring[q][k] = zero2;

    // prefetch row t=0 (yl = y0-2)
    float2 pvi[5], pvr[5];
    {
        int yl = y0 - 2;
        bool inr = (yl >= 0);
        unsigned ro = (unsigned)(inr ? yl : 0) * N;
#pragma unroll
        for (int p = 0; p < 5; p++) {
            bool ok = inr && pz[p];
            pvi[p] = ok ? __ldg((const float2*)(img + pb[p] + ro)) : zero2;
            pvr[p] = ok ? __ldg((const float2*)(ref + pb[p] + ro)) : zero2;
        }
    }
    __syncthreads();

    int buf = 0;
    for (int tb = 0; tb < 14; ++tb) {
#pragma unroll
        for (int j = 0; j < 5; ++j) {
            const int t = tb * 5 + j;

            // ---- z-summed quantities (packed) ----
            const float2 v0 = pvi[0], v1 = pvi[1], v2 = pvi[2], v3 = pvi[3], v4 = pvi[4];
            const float2 r0 = pvr[0], r1 = pvr[1], r2 = pvr[2], r3 = pvr[3], r4 = pvr[4];
            const float2 qi  = f2add(f2add(f2add(v0, v1), f2add(v2, v3)), v4);
            const float2 qr  = f2add(f2add(f2add(r0, r1), f2add(r2, r3)), r4);
            const float2 qii = f2fma(v4, v4, f2fma(v3, v3, f2fma(v2, v2, f2fma(v1, v1, f2mul(v0, v0)))));
            const float2 qrr = f2fma(r4, r4, f2fma(r3, r3, f2fma(r2, r2, f2fma(r1, r1, f2mul(r0, r0)))));
            const float2 qir = f2fma(v4, r4, f2fma(v3, r3, f2fma(v2, r2, f2fma(v1, r1, f2mul(v0, r0)))));

            *(float2*)&qz[buf][0][x0 + 2] = qi;
            *(float2*)&qz[buf][1][x0 + 2] = qr;
            *(float2*)&qz[buf][2][x0 + 2] = qii;
            *(float2*)&qz[buf][3][x0 + 2] = qrr;
            *(float2*)&qz[buf][4][x0 + 2] = qir;
            *(float2*)&cc[j][0][x0 + 2] = v2;   // center row
            *(float2*)&cc[j][1][x0 + 2] = r2;
            *(float2*)&cc[j][2][x0 + 2] = v3;   // plane z+1
            *(float2*)&cc[j][3][x0 + 2] = r3;
            *(float2*)&cc[j][4][x0 + 2] = v1;   // plane z-1
            *(float2*)&cc[j][5][x0 + 2] = r1;

            // ---- prefetch next row ----
            if (t + 1 < NSTEPS) {
                int yn = y0 - 1 + t;
                bool inr = (yn >= 0) && (yn < N);
                unsigned ro = (unsigned)(inr ? yn : 0) * N;
#pragma unroll
                for (int p = 0; p < 5; p++) {
                    bool ok = inr && pz[p];
                    pvi[p] = ok ? __ldg((const float2*)(img + pb[p] + ro)) : zero2;
                    pvr[p] = ok ? __ldg((const float2*)(ref + pb[p] + ro)) : zero2;
                }
            }
            __syncthreads();

            // ---- x-box (own value from regs, neighbors from smem) ----
            const float2 qown[5] = { qi, qr, qii, qrr, qir };
#pragma unroll
            for (int q = 0; q < 5; q++) {
                float2 a = *(const float2*)&qz[buf][q][x0];       // x0-2, x0-1
                float2 c = *(const float2*)&qz[buf][q][x0 + 4];   // x0+2, x0+3
                float2 b = qown[q];
                float s = a.y + b.x + b.y + c.x;
                ring[q][j] = f2set(s + a.x, s + c.y);             // static slot
            }
            buf ^= 1;

            // ---- epilogue for y = y0 + t - 4 ----
            if (t >= 4 && t < 68) {
                const int y = y0 + t - 4;
                const int jc = (j + 3) % 5;   // row y
                const int jp = (j + 4) % 5;   // row y+1
                const int jm = (j + 2) % 5;   // row y-1

                const float2 sum_i  = f2add(f2add(f2add(ring[0][0], ring[0][1]), f2add(ring[0][2], ring[0][3])), ring[0][4]);
                const float2 sum_r  = f2add(f2add(f2add(ring[1][0], ring[1][1]), f2add(ring[1][2], ring[1][3])), ring[1][4]);
                const float2 sum_ii = f2add(f2add(f2add(ring[2][0], ring[2][1]), f2add(ring[2][2], ring[2][3])), ring[2][4]);
                const float2 sum_rr = f2add(f2add(f2add(ring[3][0], ring[3][1]), f2add(ring[3][2], ring[3][3])), ring[3][4]);
                const float2 sum_ir = f2add(f2add(f2add(ring[4][0], ring[4][1]), f2add(ring[4][2], ring[4][3])), ring[4][4]);

                const float2 mi = f2mul(sum_i, kinv);   // faithful: ref mean uses sum_i
                const float2 t1 = f2mul(mi, k125);
                const float2 varr = f2fma(mi, f2fma(sum_r, km2, t1), sum_rr);
                const float2 vari = f2fma(mi, f2fma(sum_i, km2, t1), sum_ii);
                const float2 cross = f2fma(mi, f2fma(f2add(sum_i, sum_r), km1, t1), sum_ir);

                // all gradient operands from the cc row ring
                const float2 ciI = *(const float2*)&cc[jc][0][x0 + 2];
                const float2 ciR = *(const float2*)&cc[jc][1][x0 + 2];
                const float2 prevI = *(const float2*)&cc[jc][0][x0];
                const float2 nextI = *(const float2*)&cc[jc][0][x0 + 4];
                const float2 prevR = *(const float2*)&cc[jc][1][x0];
                const float2 nextR = *(const float2*)&cc[jc][1][x0 + 4];
                const float2 ypI = *(const float2*)&cc[jp][0][x0 + 2];
                const float2 ypR = *(const float2*)&cc[jp][1][x0 + 2];
                const float2 ymI = *(const float2*)&cc[jm][0][x0 + 2];
                const float2 ymR = *(const float2*)&cc[jm][1][x0 + 2];
                const float2 zpi = *(const float2*)&cc[jc][2][x0 + 2];
                const float2 zpr = *(const float2*)&cc[jc][3][x0 + 2];
                const float2 zmi = *(const float2*)&cc[jc][4][x0 + 2];
                const float2 zmr = *(const float2*)&cc[jc][5][x0 + 2];

                const float2 xlI = f2set(prevI.y, ciI.x);
                const float2 xrI = f2set(ciI.y, nextI.x);
                const float2 xlR = f2set(prevR.y, ciR.x);
                const float2 xrR = f2set(ciR.y, nextR.x);

                float2 gxi = f2mul(f2fma(xlI, km1, xrI), k05);
                float2 gxr = f2mul(f2fma(xlR, km1, xrR), k05);
                float2 gyi = f2mul(f2fma(ymI, km1, ypI), k05);
                float2 gyr = f2mul(f2fma(ymR, km1, ypR), k05);
                float2 gzi = f2mul(f2fma(zmi, km1, zpi), k05);
                float2 gzr = f2mul(f2fma(zmr, km1, zpr), k05);

                if (t0 == 0)   { gxi.x = ciI.y - ciI.x; gxr.x = ciR.y - ciR.x; }
                if (t0 == 127) { gxi.y = ciI.y - ciI.x; gxr.y = ciR.y - ciR.x; }
                if (y == 0)     { gyi = f2fma(ciI, km1, ypI); gyr = f2fma(ciR, km1, ypR); }
                if (y == N - 1) { gyi = f2fma(ymI, km1, ciI); gyr = f2fma(ymR, km1, ciR); }
                if (z == 0)     { gzi = f2fma(ciI, km1, zpi); gzr = f2fma(ciR, km1, zpr); }
                if (z == N - 1) { gzi = f2fma(zmi, km1, ciI); gzr = f2fma(zmr, km1, ciR); }

                const float2 gd = f2mul(f2add(gzi, gzr), k05);
                const float2 gh = f2mul(f2add(gyi, gyr), k05);
                const float2 gw = f2mul(f2add(gxi, gxr), k05);

                const float2 den = f2fma(vari, varr, keps);
                float2 rden, cv;
                rden.x = __fdividef(1.f, den.x);
                rden.y = __fdividef(1.f, den.y);
                cv.x = __fdividef(cross.x, varr.x);
                cv.y = __fdividef(cross.y, varr.y);
                const float2 inner = f2fma(f2mul(cv, km1), ciR, ciI);
                const float2 fac = f2mul(f2mul(k2, cross), f2mul(rden, inner));
                const float2 nfac = f2mul(fac, km1);

                const unsigned idx = (unsigned)z * NP + (unsigned)y * N + (unsigned)x0;
                *(float2*)(out + idx)             = f2mul(nfac, gd);
                *(float2*)(out + NVOX + idx)      = f2mul(nfac, gh);
                *(float2*)(out + 2u * NVOX + idx) = f2mul(nfac, gw);
            }
        }
    }
}

// ---------------------------------------------------------------------------
extern "C" void kernel_launch(void* const* d_in, const int* in_sizes, int n_in,
                              void* d_out, int out_size)
{
    const float* img = (const float*)d_in[0];   // image
    const float* ref = (const float*)d_in[2];   // reference_image
    float* out = (float*)d_out;

    dim3 block(128, 1, 1);
    dim3 grid(N, N / YC, 1);    // 256 z x 4 y-chunks
    ncc_fused4_kernel<<<grid, block>>>(img, ref, out);
}